// round 7
// baseline (speedup 1.0000x reference)
#include <cuda_runtime.h>
#include <cstdint>

// out[M,N] = x[M,K] @ W[N,K]^T + bias ; M=8192, N=4096, K=1024 (fp32)
// Round 7: exact fixed-point int8 IMMA path. x,w -> int16 (dynamic absmax
// scale), int16 = 256*hi + lo (int8 planes). out = s*(65536*hh + 256*mid)+bias
// with hh = sum xh*wh, mid = sum (xh*wl + xl*wh) in exact int32 accumulators
// (lo*lo dropped: ~2^-16 relative). mma.sync.m16n8k32.s8 = 2x K per instr vs
// bf16 m16n8k16 -> half the tensor-pipe instructions of the bf16x3 kernel.

#define MDIM 8192
#define NDIM 4096
#define KDIM 1024

#define BM 128
#define BN 128
#define BK 64                 // int8: 64 bytes per row per plane
#define STAGES 3
#define NCHUNK (KDIM / BK)    // 16

#define PLANEB (BM * BK)      // 8192
#define OFF_AH 0
#define OFF_AL (PLANEB)
#define OFF_BH (2 * PLANEB)
#define OFF_BL (3 * PLANEB)
#define STAGEB (4 * PLANEB)   // 32768
#define SMEM_TOTAL (STAGES * STAGEB)  // 98304

// XOR swizzle on 16B chunks within 64B rows: conflict-free ldmatrix + cp.async
#define SWZ(a) ((a) ^ (((a) >> 3) & 0x30))

// ---- static scratch (allocation-free rule) ----
__device__ __align__(256) unsigned char g_xh[MDIM * KDIM];
__device__ __align__(256) unsigned char g_xl[MDIM * KDIM];
__device__ __align__(256) unsigned char g_wh[NDIM * KDIM];
__device__ __align__(256) unsigned char g_wl[NDIM * KDIM];
__device__ unsigned int g_absmax[2];   // [0]=max|x|, [1]=max|w| (as float bits)

// ================= PTX helpers (base PTX only) =================
__device__ __forceinline__ uint32_t smem_u32(const void* p) {
    uint32_t a;
    asm("{ .reg .u64 t; cvta.to.shared.u64 t, %1; cvt.u32.u64 %0, t; }" : "=r"(a) : "l"(p));
    return a;
}
__device__ __forceinline__ void cp16(uint32_t dst, const void* src) {
    asm volatile("cp.async.cg.shared.global [%0], [%1], 16;" :: "r"(dst), "l"(src));
}
#define CP_COMMIT() asm volatile("cp.async.commit_group;" ::: "memory")
#define CP_WAIT1()  asm volatile("cp.async.wait_group 1;"  ::: "memory")
#define CP_WAIT0()  asm volatile("cp.async.wait_group 0;"  ::: "memory")

__device__ __forceinline__ void ldm_x4(uint32_t* r, uint32_t addr) {
    asm volatile("ldmatrix.sync.aligned.m8n8.x4.shared.b16 {%0,%1,%2,%3}, [%4];"
        : "=r"(r[0]), "=r"(r[1]), "=r"(r[2]), "=r"(r[3]) : "r"(addr));
}
__device__ __forceinline__ void imma16832(int* d, const uint32_t* a, const uint32_t* b) {
    asm volatile("mma.sync.aligned.m16n8k32.row.col.s32.s8.s8.s32 "
        "{%0,%1,%2,%3}, {%4,%5,%6,%7}, {%8,%9}, {%0,%1,%2,%3};"
        : "+r"(d[0]), "+r"(d[1]), "+r"(d[2]), "+r"(d[3])
        : "r"(a[0]), "r"(a[1]), "r"(a[2]), "r"(a[3]), "r"(b[0]), "r"(b[1]));
}

// ================= prep kernels =================
__global__ void reset_kernel() { g_absmax[0] = 0u; g_absmax[1] = 0u; }

__global__ void absmax_kernel(const float* __restrict__ x, int n4x,
                              const float* __restrict__ w, int n4w)
{
    float mx = 0.f, mw = 0.f;
    const int stride = gridDim.x * blockDim.x;
    for (int i = blockIdx.x * blockDim.x + threadIdx.x; i < n4x; i += stride) {
        float4 v = reinterpret_cast<const float4*>(x)[i];
        mx = fmaxf(mx, fmaxf(fmaxf(fabsf(v.x), fabsf(v.y)), fmaxf(fabsf(v.z), fabsf(v.w))));
    }
    for (int i = blockIdx.x * blockDim.x + threadIdx.x; i < n4w; i += stride) {
        float4 v = reinterpret_cast<const float4*>(w)[i];
        mw = fmaxf(mw, fmaxf(fmaxf(fabsf(v.x), fabsf(v.y)), fmaxf(fabsf(v.z), fabsf(v.w))));
    }
    #pragma unroll
    for (int o = 16; o; o >>= 1) {
        mx = fmaxf(mx, __shfl_xor_sync(0xFFFFFFFFu, mx, o));
        mw = fmaxf(mw, __shfl_xor_sync(0xFFFFFFFFu, mw, o));
    }
    if ((threadIdx.x & 31) == 0) {
        atomicMax(&g_absmax[0], __float_as_uint(mx));
        atomicMax(&g_absmax[1], __float_as_uint(mw));
    }
}

__global__ void quant_kernel(const float* __restrict__ x, const float* __restrict__ w,
                             int n4x, int n4tot)
{
    int i = blockIdx.x * blockDim.x + threadIdx.x;
    if (i >= n4tot) return;
    const float* src;
    unsigned char *dh, *dl;
    int idx;
    float inv;
    if (i < n4x) { src = x; dh = g_xh; dl = g_xl; idx = i;
                   inv = __fdividef(32000.f, __uint_as_float(g_absmax[0])); }
    else         { src = w; dh = g_wh; dl = g_wl; idx = i - n4x;
                   inv = __fdividef(32000.f, __uint_as_float(g_absmax[1])); }

    float4 v = reinterpret_cast<const float4*>(src)[idx];
    float vs[4] = {v.x, v.y, v.z, v.w};
    unsigned hp = 0, lp = 0;
    #pragma unroll
    for (int j = 0; j < 4; j++) {
        int q = __float2int_rn(vs[j] * inv);      // |q| <= 32000
        int h = (q + 128) >> 8;                    // [-124, 126]
        int l = q - (h << 8);                      // [-128, 127]
        hp |= ((unsigned)(h & 255)) << (8 * j);
        lp |= ((unsigned)(l & 255)) << (8 * j);
    }
    reinterpret_cast<unsigned*>(dh)[idx] = hp;
    reinterpret_cast<unsigned*>(dl)[idx] = lp;
}

// ================= main GEMM kernel =================
__global__ void __launch_bounds__(512, 1)
qgemm_i8(const float* __restrict__ bias, float* __restrict__ C)
{
    extern __shared__ char smem[];
    const uint32_t sbase = smem_u32(smem);
    const int tid  = threadIdx.x;
    const int wid  = tid >> 5;
    const int lane = tid & 31;
    const int bm = blockIdx.y * BM;
    const int bn = blockIdx.x * BN;
    const int wm = (wid >> 2) * 32;   // warp row offset (0,32,64,96)
    const int wn = (wid & 3) * 32;    // warp col offset (0,32,64,96)

    int acc_hh[2][4][4], acc_mid[2][4][4];
    #pragma unroll
    for (int a = 0; a < 2; a++)
        #pragma unroll
        for (int b = 0; b < 4; b++)
            #pragma unroll
            for (int k = 0; k < 4; k++) { acc_hh[a][b][k] = 0; acc_mid[a][b][k] = 0; }

    // loader: 512 threads x 4 planes x 16B = 32KB/stage
    const int lrow = tid >> 2;        // 0..127
    const int lc   = tid & 3;
    const uint32_t dsw = SWZ((uint32_t)(lrow * 64 + lc * 16));
    const unsigned char* pAh = g_xh + (size_t)(bm + lrow) * KDIM + lc * 16;
    const unsigned char* pAl = g_xl + (size_t)(bm + lrow) * KDIM + lc * 16;
    const unsigned char* pBh = g_wh + (size_t)(bn + lrow) * KDIM + lc * 16;
    const unsigned char* pBl = g_wl + (size_t)(bn + lrow) * KDIM + lc * 16;

    auto issue = [&](int chunk, int stage) {
        const uint32_t sst = sbase + stage * STAGEB;
        const size_t ko = (size_t)chunk * BK;
        cp16(sst + OFF_AH + dsw, pAh + ko);
        cp16(sst + OFF_AL + dsw, pAl + ko);
        cp16(sst + OFF_BH + dsw, pBh + ko);
        cp16(sst + OFF_BL + dsw, pBl + ko);
        CP_COMMIT();
    };
    issue(0, 0);
    issue(1, 1);

    // ldmatrix fragment offsets (plane-relative, swizzled)
    // A (m16k32): lanes 0-7 rows0-7@k0 | 8-15 rows8-15@k0 | 16-23 rows0-7@k16 | 24-31 rows8-15@k16
    // B (two n8 blocks): lanes 0-7 n0-7@k0 | 8-15 n0-7@k16 | 16-23 n8-15@k0 | 24-31 n8-15@k16
    uint32_t aoff[2][2], boff[2][2];
    #pragma unroll
    for (int mb = 0; mb < 2; mb++)
        #pragma unroll
        for (int ks = 0; ks < 2; ks++)
            aoff[mb][ks] = SWZ((uint32_t)((wm + mb * 16 + (lane & 15)) * 64 +
                                          ks * 32 + (lane >> 4) * 16));
    #pragma unroll
    for (int p = 0; p < 2; p++)
        #pragma unroll
        for (int ks = 0; ks < 2; ks++)
            boff[p][ks] = SWZ((uint32_t)((wn + p * 16 + (lane & 7) + ((lane >> 4) << 3)) * 64 +
                                         ks * 32 + ((lane >> 3) & 1) * 16));

    for (int c = 0; c < NCHUNK; c++) {
        if (c == NCHUNK - 1) { CP_WAIT0(); } else { CP_WAIT1(); }
        __syncthreads();
        if (c + 2 < NCHUNK) issue(c + 2, (c + 2) % STAGES);

        const uint32_t sst = sbase + (c % STAGES) * STAGEB;
        #pragma unroll
        for (int ks = 0; ks < 2; ks++) {
            uint32_t bh[4][2], bl[4][2];
            #pragma unroll
            for (int p = 0; p < 2; p++) {
                uint32_t r[4];
                ldm_x4(r, sst + OFF_BH + boff[p][ks]);
                bh[p*2][0] = r[0]; bh[p*2][1] = r[1];
                bh[p*2+1][0] = r[2]; bh[p*2+1][1] = r[3];
                ldm_x4(r, sst + OFF_BL + boff[p][ks]);
                bl[p*2][0] = r[0]; bl[p*2][1] = r[1];
                bl[p*2+1][0] = r[2]; bl[p*2+1][1] = r[3];
            }
            #pragma unroll
            for (int mb = 0; mb < 2; mb++) {
                uint32_t ah[4], al[4];
                ldm_x4(ah, sst + OFF_AH + aoff[mb][ks]);
                ldm_x4(al, sst + OFF_AL + aoff[mb][ks]);
                #pragma unroll
                for (int nb = 0; nb < 4; nb++)
                    imma16832(acc_hh[mb][nb], ah, bh[nb]);
                #pragma unroll
                for (int nb = 0; nb < 4; nb++)
                    imma16832(acc_mid[mb][nb], ah, bl[nb]);
                #pragma unroll
                for (int nb = 0; nb < 4; nb++)
                    imma16832(acc_mid[mb][nb], al, bh[nb]);
            }
        }
    }

    // -------- epilogue: combine, scale, + bias, store --------
    const float s = (__uint_as_float(g_absmax[0]) * __uint_as_float(g_absmax[1]))
                    * (1.0f / (32000.f * 32000.f));
    const float s1 = s * 65536.f;
    const float s2 = s * 256.f;

    const int g  = lane >> 2;
    const int tg = lane & 3;
    #pragma unroll
    for (int mb = 0; mb < 2; mb++) {
        #pragma unroll
        for (int nb = 0; nb < 4; nb++) {
            const int col = bn + wn + nb * 8 + tg * 2;
            const float2 bv = *reinterpret_cast<const float2*>(bias + col);
            const int r0 = bm + wm + mb * 16 + g;
            const int* hh = acc_hh[mb][nb];
            const int* md = acc_mid[mb][nb];
            float2 o0, o1;
            o0.x = fmaf((float)hh[0], s1, fmaf((float)md[0], s2, bv.x));
            o0.y = fmaf((float)hh[1], s1, fmaf((float)md[1], s2, bv.y));
            o1.x = fmaf((float)hh[2], s1, fmaf((float)md[2], s2, bv.x));
            o1.y = fmaf((float)hh[3], s1, fmaf((float)md[3], s2, bv.y));
            *reinterpret_cast<float2*>(C + (size_t)r0 * NDIM + col) = o0;
            *reinterpret_cast<float2*>(C + (size_t)(r0 + 8) * NDIM + col) = o1;
        }
    }
}

// ================= host side =================
extern "C" void kernel_launch(void* const* d_in, const int* in_sizes, int n_in,
                              void* d_out, int out_size)
{
    const float* x    = (const float*)d_in[0];   // [M, K]
    const float* w    = (const float*)d_in[1];   // [N, K]
    const float* bias = (const float*)d_in[2];   // [N]
    float* out        = (float*)d_out;           // [M, N]

    const int n4x = MDIM * KDIM / 4;
    const int n4w = NDIM * KDIM / 4;
    const int n4tot = n4x + n4w;

    reset_kernel<<<1, 1>>>();
    absmax_kernel<<<1184, 256>>>(x, n4x, w, n4w);
    quant_kernel<<<(n4tot + 255) / 256, 256>>>(x, w, n4x, n4tot);

    static bool attr_set = false;
    if (!attr_set) {
        cudaFuncSetAttribute(qgemm_i8, cudaFuncAttributeMaxDynamicSharedMemorySize, SMEM_TOTAL);
        attr_set = true;
    }
    dim3 grid(NDIM / BN, MDIM / BM);   // (32, 64)
    qgemm_i8<<<grid, 512, SMEM_TOTAL>>>(bias, out);
}

// round 8
// speedup vs baseline: 2.7286x; 2.7286x over previous
#include <cuda_runtime.h>
#include <cuda_bf16.h>
#include <cstdint>

// out[M,N] = x[M,K] @ W[N,K]^T + bias ; M=8192, N=4096, K=1024 (fp32)
// bf16x3 split GEMM on mma.sync HMMA (the only native legacy tensor path on
// sm_103; int8/fp8 legacy mma is emulated & slow). Round 8: 6-stage pipeline,
// barrier every 2 chunks, 32x32 warp tiles (3:1 MMA:LDSM), swizzled 64B rows.

#define MDIM 8192
#define NDIM 4096
#define KDIM 1024

#define BM 128
#define BN 128
#define BK 32                 // bf16: 64 B per row per plane
#define STAGES 6
#define NCHUNK (KDIM / BK)    // 32
#define NPAIR (NCHUNK / 2)    // 16

#define PLANEB (BM * 64)      // 8192 B (128 rows x 64 B)
#define OFF_AH 0
#define OFF_AL (PLANEB)
#define OFF_BH (2 * PLANEB)
#define OFF_BL (3 * PLANEB)
#define STAGEB (4 * PLANEB)   // 32768
#define SMEM_TOTAL (STAGES * STAGEB)  // 196608

// XOR swizzle on 16B chunks within 64B rows (conflict-free ldmatrix + cp.async)
#define SWZ(a) ((a) ^ (((a) >> 3) & 0x30))

// ---- static scratch for split operands ----
__device__ __align__(256) __nv_bfloat16 g_Ah[MDIM * KDIM];
__device__ __align__(256) __nv_bfloat16 g_Al[MDIM * KDIM];
__device__ __align__(256) __nv_bfloat16 g_Bh[NDIM * KDIM];
__device__ __align__(256) __nv_bfloat16 g_Bl[NDIM * KDIM];

// ================= PTX helpers (base PTX only) =================
__device__ __forceinline__ uint32_t smem_u32(const void* p) {
    uint32_t a;
    asm("{ .reg .u64 t; cvta.to.shared.u64 t, %1; cvt.u32.u64 %0, t; }" : "=r"(a) : "l"(p));
    return a;
}
__device__ __forceinline__ void cp16(uint32_t dst, const void* src) {
    asm volatile("cp.async.cg.shared.global [%0], [%1], 16;" :: "r"(dst), "l"(src));
}
#define CP_COMMIT() asm volatile("cp.async.commit_group;" ::: "memory")
#define CP_WAIT2()  asm volatile("cp.async.wait_group 2;"  ::: "memory")
#define CP_WAIT0()  asm volatile("cp.async.wait_group 0;"  ::: "memory")

__device__ __forceinline__ void ldm_x4(uint32_t* r, uint32_t addr) {
    asm volatile("ldmatrix.sync.aligned.m8n8.x4.shared.b16 {%0,%1,%2,%3}, [%4];"
        : "=r"(r[0]), "=r"(r[1]), "=r"(r[2]), "=r"(r[3]) : "r"(addr));
}
__device__ __forceinline__ void mma16816(float* d, const uint32_t* a, const uint32_t* b) {
    asm volatile("mma.sync.aligned.m16n8k16.row.col.f32.bf16.bf16.f32 "
        "{%0,%1,%2,%3}, {%4,%5,%6,%7}, {%8,%9}, {%0,%1,%2,%3};"
        : "+f"(d[0]), "+f"(d[1]), "+f"(d[2]), "+f"(d[3])
        : "r"(a[0]), "r"(a[1]), "r"(a[2]), "r"(a[3]), "r"(b[0]), "r"(b[1]));
}

// ================= merged split kernel: fp32 -> (bf16 hi, bf16 lo) =================
__global__ void split_both_kernel(const float* __restrict__ srcA,
                                  const float* __restrict__ srcB,
                                  __nv_bfloat16* __restrict__ hiA, __nv_bfloat16* __restrict__ loA,
                                  __nv_bfloat16* __restrict__ hiB, __nv_bfloat16* __restrict__ loB,
                                  int n4a, int n4tot)
{
    int i = blockIdx.x * blockDim.x + threadIdx.x;
    if (i >= n4tot) return;
    const float* src;
    __nv_bfloat16 *hi, *lo;
    int idx;
    if (i < n4a) { src = srcA; hi = hiA; lo = loA; idx = i; }
    else         { src = srcB; hi = hiB; lo = loB; idx = i - n4a; }

    float4 v = reinterpret_cast<const float4*>(src)[idx];
    float vs[4] = {v.x, v.y, v.z, v.w};
    unsigned short hs[4], ls[4];
    #pragma unroll
    for (int j = 0; j < 4; j++) {
        __nv_bfloat16 h = __float2bfloat16(vs[j]);
        __nv_bfloat16 l = __float2bfloat16(vs[j] - __bfloat162float(h));
        hs[j] = ((__nv_bfloat16_raw)h).x;
        ls[j] = ((__nv_bfloat16_raw)l).x;
    }
    ushort4 ho = {hs[0], hs[1], hs[2], hs[3]};
    ushort4 lv = {ls[0], ls[1], ls[2], ls[3]};
    reinterpret_cast<ushort4*>(hi)[idx] = ho;
    reinterpret_cast<ushort4*>(lo)[idx] = lv;
}

// ================= main GEMM kernel =================
__global__ void __launch_bounds__(512, 1)
qgemm_mma(const __nv_bfloat16* __restrict__ Ah, const __nv_bfloat16* __restrict__ Al,
          const __nv_bfloat16* __restrict__ Bh, const __nv_bfloat16* __restrict__ Bl,
          const float* __restrict__ bias, float* __restrict__ C)
{
    extern __shared__ char smem[];
    const uint32_t sbase = smem_u32(smem);
    const int tid  = threadIdx.x;
    const int wid  = tid >> 5;
    const int lane = tid & 31;
    const int bm = blockIdx.y * BM;
    const int bn = blockIdx.x * BN;
    const int wm = (wid >> 2) * 32;   // warp row offset (0,32,64,96)
    const int wn = (wid & 3) * 32;    // warp col offset (0,32,64,96)

    float acc[2][4][4];
    #pragma unroll
    for (int a = 0; a < 2; a++)
        #pragma unroll
        for (int b = 0; b < 4; b++)
            #pragma unroll
            for (int k = 0; k < 4; k++)
                acc[a][b][k] = 0.0f;

    // loader: 512 threads x 4 planes x 16B = 32KB/stage (1 cp16 per plane each)
    const int lrow = tid >> 2;        // 0..127
    const int lc   = tid & 3;
    const uint32_t dsw = SWZ((uint32_t)(lrow * 64 + lc * 16));
    const char* pAh = (const char*)Ah + (size_t)(bm + lrow) * (KDIM * 2) + lc * 16;
    const char* pAl = (const char*)Al + (size_t)(bm + lrow) * (KDIM * 2) + lc * 16;
    const char* pBh = (const char*)Bh + (size_t)(bn + lrow) * (KDIM * 2) + lc * 16;
    const char* pBl = (const char*)Bl + (size_t)(bn + lrow) * (KDIM * 2) + lc * 16;

    auto issue = [&](int chunk) {
        const uint32_t sst = sbase + (chunk % STAGES) * STAGEB;
        const size_t ko = (size_t)chunk * (BK * 2);
        cp16(sst + OFF_AH + dsw, pAh + ko);
        cp16(sst + OFF_AL + dsw, pAl + ko);
        cp16(sst + OFF_BH + dsw, pBh + ko);
        cp16(sst + OFF_BL + dsw, pBl + ko);
        CP_COMMIT();
    };
    issue(0); issue(1); issue(2); issue(3);

    // ldmatrix fragment offsets (plane-relative, swizzled), ks in {0,1} = k16 half
    uint32_t aoff[2][2], boff[2][2];
    #pragma unroll
    for (int mb = 0; mb < 2; mb++)
        #pragma unroll
        for (int ks = 0; ks < 2; ks++)
            aoff[mb][ks] = SWZ((uint32_t)((wm + mb * 16 + (lane & 15)) * 64 +
                                          ks * 32 + (lane >> 4) * 16));
    #pragma unroll
    for (int p = 0; p < 2; p++)
        #pragma unroll
        for (int ks = 0; ks < 2; ks++)
            boff[p][ks] = SWZ((uint32_t)((wn + p * 16 + (lane & 7) + ((lane >> 4) << 3)) * 64 +
                                         ks * 32 + ((lane >> 3) & 1) * 16));

    // compute one k16 step from the stage holding `chunk`
    auto do_ks = [&](int chunk, int ks) {
        const uint32_t sst = sbase + (chunk % STAGES) * STAGEB;
        uint32_t bh[4][2], bl[4][2];
        #pragma unroll
        for (int p = 0; p < 2; p++) {
            uint32_t r[4];
            ldm_x4(r, sst + OFF_BH + boff[p][ks]);
            bh[p*2][0] = r[0]; bh[p*2][1] = r[1];
            bh[p*2+1][0] = r[2]; bh[p*2+1][1] = r[3];
            ldm_x4(r, sst + OFF_BL + boff[p][ks]);
            bl[p*2][0] = r[0]; bl[p*2][1] = r[1];
            bl[p*2+1][0] = r[2]; bl[p*2+1][1] = r[3];
        }
        #pragma unroll
        for (int mb = 0; mb < 2; mb++) {
            uint32_t ah[4], al[4];
            ldm_x4(ah, sst + OFF_AH + aoff[mb][ks]);
            ldm_x4(al, sst + OFF_AL + aoff[mb][ks]);
            #pragma unroll
            for (int nb = 0; nb < 4; nb++)
                mma16816(acc[mb][nb], ah, bh[nb]);
            #pragma unroll
            for (int nb = 0; nb < 4; nb++)
                mma16816(acc[mb][nb], ah, bl[nb]);
            #pragma unroll
            for (int nb = 0; nb < 4; nb++)
                mma16816(acc[mb][nb], al, bh[nb]);
        }
    };

    // pair loop: one barrier per 2 chunks; 6 stages keep writes clear of any
    // stage a skewed warp could still be reading inside a barrier window.
    for (int p = 0; p < NPAIR; p++) {
        const int c = 2 * p;
        if (p == NPAIR - 1) { CP_WAIT0(); } else { CP_WAIT2(); }  // chunks c, c+1 landed
        __syncthreads();

        do_ks(c, 0);   do_ks(c, 1);
        do_ks(c + 1, 0); do_ks(c + 1, 1);

        if (c + 4 < NCHUNK) issue(c + 4);
        if (c + 5 < NCHUNK) issue(c + 5);
    }

    // -------- epilogue: + bias, store --------
    const int g  = lane >> 2;
    const int tg = lane & 3;
    #pragma unroll
    for (int mb = 0; mb < 2; mb++) {
        #pragma unroll
        for (int nb = 0; nb < 4; nb++) {
            const int col = bn + wn + nb * 8 + tg * 2;
            const float2 bv = *reinterpret_cast<const float2*>(bias + col);
            const int r0 = bm + wm + mb * 16 + g;
            float2 o0 = {acc[mb][nb][0] + bv.x, acc[mb][nb][1] + bv.y};
            float2 o1 = {acc[mb][nb][2] + bv.x, acc[mb][nb][3] + bv.y};
            *reinterpret_cast<float2*>(C + (size_t)r0 * NDIM + col) = o0;
            *reinterpret_cast<float2*>(C + (size_t)(r0 + 8) * NDIM + col) = o1;
        }
    }
}

// ================= host side =================
extern "C" void kernel_launch(void* const* d_in, const int* in_sizes, int n_in,
                              void* d_out, int out_size)
{
    const float* x    = (const float*)d_in[0];   // [M, K]
    const float* w    = (const float*)d_in[1];   // [N, K]
    const float* bias = (const float*)d_in[2];   // [N]
    float* out        = (float*)d_out;           // [M, N]

    void *pAh, *pAl, *pBh, *pBl;
    cudaGetSymbolAddress(&pAh, g_Ah);
    cudaGetSymbolAddress(&pAl, g_Al);
    cudaGetSymbolAddress(&pBh, g_Bh);
    cudaGetSymbolAddress(&pBl, g_Bl);

    int n4a = MDIM * KDIM / 4;
    int n4b = NDIM * KDIM / 4;
    int n4tot = n4a + n4b;
    split_both_kernel<<<(n4tot + 255) / 256, 256>>>(
        x, w,
        (__nv_bfloat16*)pAh, (__nv_bfloat16*)pAl,
        (__nv_bfloat16*)pBh, (__nv_bfloat16*)pBl, n4a, n4tot);

    static bool attr_set = false;
    if (!attr_set) {
        cudaFuncSetAttribute(qgemm_mma, cudaFuncAttributeMaxDynamicSharedMemorySize, SMEM_TOTAL);
        attr_set = true;
    }
    dim3 grid(NDIM / BN, MDIM / BM);   // (32, 64) = 2048 CTAs
    qgemm_mma<<<grid, 512, SMEM_TOTAL>>>((const __nv_bfloat16*)pAh, (const __nv_bfloat16*)pAl,
                                         (const __nv_bfloat16*)pBh, (const __nv_bfloat16*)pBl,
                                         bias, out);
}

// round 9
// speedup vs baseline: 4.0897x; 1.4988x over previous
#include <cuda_runtime.h>
#include <cuda_fp16.h>
#include <cstdint>

// out[M,N] = x[M,K] @ W[N,K]^T + bias ; M=8192, N=4096, K=1024 (fp32)
// Round 9: fp16 2-pass GEMM on mma.sync HMMA.
//   x = Ah + Al (fp16 hi/lo, exact to ~2^-22); w = Bh (single fp16, the only
//   error source, ~1.9e-4 RMS). C = Ah*Bh + Al*Bh -> 2 MMA passes instead of
//   bf16x3's 3 passes. Legacy HMMA issue floor ~3cyc/MMA/SM => ~340us GEMM.

#define MDIM 8192
#define NDIM 4096
#define KDIM 1024

#define BM 128
#define BN 128
#define BK 32                 // fp16: 64 B per row per plane
#define STAGES 6
#define NCHUNK (KDIM / BK)    // 32
#define NPAIR (NCHUNK / 2)    // 16

#define PLANEB (BM * 64)      // 8192 B (128 rows x 64 B)
#define OFF_AH 0
#define OFF_AL (PLANEB)
#define OFF_BH (2 * PLANEB)
#define STAGEB (3 * PLANEB)   // 24576
#define SMEM_TOTAL (STAGES * STAGEB)  // 147456

// XOR swizzle on 16B chunks within 64B rows (conflict-free ldmatrix + cp.async)
#define SWZ(a) ((a) ^ (((a) >> 3) & 0x30))

// ---- static scratch for split operands ----
__device__ __align__(256) __half g_Ah[MDIM * KDIM];
__device__ __align__(256) __half g_Al[MDIM * KDIM];
__device__ __align__(256) __half g_Bh[NDIM * KDIM];

// ================= PTX helpers (base PTX only) =================
__device__ __forceinline__ uint32_t smem_u32(const void* p) {
    uint32_t a;
    asm("{ .reg .u64 t; cvta.to.shared.u64 t, %1; cvt.u32.u64 %0, t; }" : "=r"(a) : "l"(p));
    return a;
}
__device__ __forceinline__ void cp16(uint32_t dst, const void* src) {
    asm volatile("cp.async.cg.shared.global [%0], [%1], 16;" :: "r"(dst), "l"(src));
}
#define CP_COMMIT() asm volatile("cp.async.commit_group;" ::: "memory")
#define CP_WAIT2()  asm volatile("cp.async.wait_group 2;"  ::: "memory")
#define CP_WAIT0()  asm volatile("cp.async.wait_group 0;"  ::: "memory")

__device__ __forceinline__ void ldm_x4(uint32_t* r, uint32_t addr) {
    asm volatile("ldmatrix.sync.aligned.m8n8.x4.shared.b16 {%0,%1,%2,%3}, [%4];"
        : "=r"(r[0]), "=r"(r[1]), "=r"(r[2]), "=r"(r[3]) : "r"(addr));
}
__device__ __forceinline__ void mma16816(float* d, const uint32_t* a, const uint32_t* b) {
    asm volatile("mma.sync.aligned.m16n8k16.row.col.f32.f16.f16.f32 "
        "{%0,%1,%2,%3}, {%4,%5,%6,%7}, {%8,%9}, {%0,%1,%2,%3};"
        : "+f"(d[0]), "+f"(d[1]), "+f"(d[2]), "+f"(d[3])
        : "r"(a[0]), "r"(a[1]), "r"(a[2]), "r"(a[3]), "r"(b[0]), "r"(b[1]));
}

// ================= prep: x -> fp16 hi/lo ; w -> fp16 =================
__global__ void prep_kernel(const float* __restrict__ x,
                            const float* __restrict__ w,
                            int n4x, int n4tot)
{
    int i = blockIdx.x * blockDim.x + threadIdx.x;
    if (i >= n4tot) return;
    if (i < n4x) {
        float4 v = reinterpret_cast<const float4*>(x)[i];
        float vs[4] = {v.x, v.y, v.z, v.w};
        unsigned short hs[4], ls[4];
        #pragma unroll
        for (int j = 0; j < 4; j++) {
            __half h = __float2half_rn(vs[j]);
            __half l = __float2half_rn(vs[j] - __half2float(h));
            hs[j] = ((__half_raw)h).x;
            ls[j] = ((__half_raw)l).x;
        }
        ushort4 ho = {hs[0], hs[1], hs[2], hs[3]};
        ushort4 lv = {ls[0], ls[1], ls[2], ls[3]};
        reinterpret_cast<ushort4*>(g_Ah)[i] = ho;
        reinterpret_cast<ushort4*>(g_Al)[i] = lv;
    } else {
        int idx = i - n4x;
        float4 v = reinterpret_cast<const float4*>(w)[idx];
        unsigned short hs[4];
        hs[0] = ((__half_raw)__float2half_rn(v.x)).x;
        hs[1] = ((__half_raw)__float2half_rn(v.y)).x;
        hs[2] = ((__half_raw)__float2half_rn(v.z)).x;
        hs[3] = ((__half_raw)__float2half_rn(v.w)).x;
        ushort4 ho = {hs[0], hs[1], hs[2], hs[3]};
        reinterpret_cast<ushort4*>(g_Bh)[idx] = ho;
    }
}

// ================= main GEMM kernel =================
__global__ void __launch_bounds__(512, 1)
qgemm_fp16x2(const float* __restrict__ bias, float* __restrict__ C)
{
    extern __shared__ char smem[];
    const uint32_t sbase = smem_u32(smem);
    const int tid  = threadIdx.x;
    const int wid  = tid >> 5;
    const int lane = tid & 31;
    const int bm = blockIdx.y * BM;
    const int bn = blockIdx.x * BN;
    const int wm = (wid >> 2) * 32;   // warp row offset (0,32,64,96)
    const int wn = (wid & 3) * 32;    // warp col offset (0,32,64,96)

    float acc[2][4][4];
    #pragma unroll
    for (int a = 0; a < 2; a++)
        #pragma unroll
        for (int b = 0; b < 4; b++)
            #pragma unroll
            for (int k = 0; k < 4; k++)
                acc[a][b][k] = 0.0f;

    // loader: 512 threads x 3 planes x 16B = 24KB/stage
    const int lrow = tid >> 2;        // 0..127
    const int lc   = tid & 3;
    const uint32_t dsw = SWZ((uint32_t)(lrow * 64 + lc * 16));
    const char* pAh = (const char*)g_Ah + (size_t)(bm + lrow) * (KDIM * 2) + lc * 16;
    const char* pAl = (const char*)g_Al + (size_t)(bm + lrow) * (KDIM * 2) + lc * 16;
    const char* pBh = (const char*)g_Bh + (size_t)(bn + lrow) * (KDIM * 2) + lc * 16;

    auto issue = [&](int chunk) {
        const uint32_t sst = sbase + (chunk % STAGES) * STAGEB;
        const size_t ko = (size_t)chunk * (BK * 2);
        cp16(sst + OFF_AH + dsw, pAh + ko);
        cp16(sst + OFF_AL + dsw, pAl + ko);
        cp16(sst + OFF_BH + dsw, pBh + ko);
        CP_COMMIT();
    };
    issue(0); issue(1); issue(2); issue(3);

    // ldmatrix fragment offsets (plane-relative, swizzled), ks = k16 half
    uint32_t aoff[2][2], boff[2][2];
    #pragma unroll
    for (int mb = 0; mb < 2; mb++)
        #pragma unroll
        for (int ks = 0; ks < 2; ks++)
            aoff[mb][ks] = SWZ((uint32_t)((wm + mb * 16 + (lane & 15)) * 64 +
                                          ks * 32 + (lane >> 4) * 16));
    #pragma unroll
    for (int p = 0; p < 2; p++)
        #pragma unroll
        for (int ks = 0; ks < 2; ks++)
            boff[p][ks] = SWZ((uint32_t)((wn + p * 16 + (lane & 7) + ((lane >> 4) << 3)) * 64 +
                                         ks * 32 + ((lane >> 3) & 1) * 16));

    auto do_ks = [&](int chunk, int ks) {
        const uint32_t sst = sbase + (chunk % STAGES) * STAGEB;
        uint32_t bh[4][2];
        #pragma unroll
        for (int p = 0; p < 2; p++) {
            uint32_t r[4];
            ldm_x4(r, sst + OFF_BH + boff[p][ks]);
            bh[p*2][0] = r[0]; bh[p*2][1] = r[1];
            bh[p*2+1][0] = r[2]; bh[p*2+1][1] = r[3];
        }
        #pragma unroll
        for (int mb = 0; mb < 2; mb++) {
            uint32_t ah[4], al[4];
            ldm_x4(ah, sst + OFF_AH + aoff[mb][ks]);
            ldm_x4(al, sst + OFF_AL + aoff[mb][ks]);
            #pragma unroll
            for (int nb = 0; nb < 4; nb++)
                mma16816(acc[mb][nb], ah, bh[nb]);
            #pragma unroll
            for (int nb = 0; nb < 4; nb++)
                mma16816(acc[mb][nb], al, bh[nb]);
        }
    };

    for (int p = 0; p < NPAIR; p++) {
        const int c = 2 * p;
        if (p == NPAIR - 1) { CP_WAIT0(); } else { CP_WAIT2(); }
        __syncthreads();

        do_ks(c, 0);     do_ks(c, 1);
        do_ks(c + 1, 0); do_ks(c + 1, 1);

        if (c + 4 < NCHUNK) issue(c + 4);
        if (c + 5 < NCHUNK) issue(c + 5);
    }

    // -------- epilogue: + bias, store --------
    const int g  = lane >> 2;
    const int tg = lane & 3;
    #pragma unroll
    for (int mb = 0; mb < 2; mb++) {
        #pragma unroll
        for (int nb = 0; nb < 4; nb++) {
            const int col = bn + wn + nb * 8 + tg * 2;
            const float2 bv = *reinterpret_cast<const float2*>(bias + col);
            const int r0 = bm + wm + mb * 16 + g;
            float2 o0 = {acc[mb][nb][0] + bv.x, acc[mb][nb][1] + bv.y};
            float2 o1 = {acc[mb][nb][2] + bv.x, acc[mb][nb][3] + bv.y};
            *reinterpret_cast<float2*>(C + (size_t)r0 * NDIM + col) = o0;
            *reinterpret_cast<float2*>(C + (size_t)(r0 + 8) * NDIM + col) = o1;
        }
    }
}

// ================= host side =================
extern "C" void kernel_launch(void* const* d_in, const int* in_sizes, int n_in,
                              void* d_out, int out_size)
{
    const float* x    = (const float*)d_in[0];   // [M, K]
    const float* w    = (const float*)d_in[1];   // [N, K]
    const float* bias = (const float*)d_in[2];   // [N]
    float* out        = (float*)d_out;           // [M, N]

    const int n4x = MDIM * KDIM / 4;
    const int n4w = NDIM * KDIM / 4;
    const int n4tot = n4x + n4w;
    prep_kernel<<<(n4tot + 255) / 256, 256>>>(x, w, n4x, n4tot);

    static bool attr_set = false;
    if (!attr_set) {
        cudaFuncSetAttribute(qgemm_fp16x2, cudaFuncAttributeMaxDynamicSharedMemorySize, SMEM_TOTAL);
        attr_set = true;
    }
    dim3 grid(NDIM / BN, MDIM / BM);   // (32, 64) = 2048 CTAs
    qgemm_fp16x2<<<grid, 512, SMEM_TOTAL>>>(bias, out);
}

// round 10
// speedup vs baseline: 5.9334x; 1.4508x over previous
#include <cuda_runtime.h>
#include <cuda_fp16.h>
#include <cstdint>

// out[M,N] = x[M,K] @ W[N,K]^T + bias ; M=8192, N=4096, K=1024 (fp32)
// Round 10: single-pass fp16 HMMA GEMM. Both x and w rounded to fp16
// (each ~1.9e-4 RMS relative; combined ~2.6e-4, gate is 1e-3).
// Legacy mma.sync costs ~3 cyc/MMA/SM on sm_103 -> runtime ~ MMA count:
// 16.8M MMAs => ~170us GEMM + ~15us prep.

#define MDIM 8192
#define NDIM 4096
#define KDIM 1024

#define BM 128
#define BN 128
#define BK 32                 // fp16: 64 B per row per plane
#define STAGES 6
#define NCHUNK (KDIM / BK)    // 32
#define NPAIR (NCHUNK / 2)    // 16

#define PLANEB (BM * 64)      // 8192 B (128 rows x 64 B)
#define OFF_A 0
#define OFF_B (PLANEB)
#define STAGEB (2 * PLANEB)   // 16384
#define SMEM_TOTAL (STAGES * STAGEB)  // 98304

// XOR swizzle on 16B chunks within 64B rows (conflict-free ldmatrix + cp.async)
#define SWZ(a) ((a) ^ (((a) >> 3) & 0x30))

// ---- static scratch for fp16 operands ----
__device__ __align__(256) __half g_A[MDIM * KDIM];
__device__ __align__(256) __half g_B[NDIM * KDIM];

// ================= PTX helpers (base PTX only) =================
__device__ __forceinline__ uint32_t smem_u32(const void* p) {
    uint32_t a;
    asm("{ .reg .u64 t; cvta.to.shared.u64 t, %1; cvt.u32.u64 %0, t; }" : "=r"(a) : "l"(p));
    return a;
}
__device__ __forceinline__ void cp16(uint32_t dst, const void* src) {
    asm volatile("cp.async.cg.shared.global [%0], [%1], 16;" :: "r"(dst), "l"(src));
}
#define CP_COMMIT() asm volatile("cp.async.commit_group;" ::: "memory")
#define CP_WAIT2()  asm volatile("cp.async.wait_group 2;"  ::: "memory")
#define CP_WAIT0()  asm volatile("cp.async.wait_group 0;"  ::: "memory")

__device__ __forceinline__ void ldm_x4(uint32_t* r, uint32_t addr) {
    asm volatile("ldmatrix.sync.aligned.m8n8.x4.shared.b16 {%0,%1,%2,%3}, [%4];"
        : "=r"(r[0]), "=r"(r[1]), "=r"(r[2]), "=r"(r[3]) : "r"(addr));
}
__device__ __forceinline__ void mma16816(float* d, const uint32_t* a, const uint32_t* b) {
    asm volatile("mma.sync.aligned.m16n8k16.row.col.f32.f16.f16.f32 "
        "{%0,%1,%2,%3}, {%4,%5,%6,%7}, {%8,%9}, {%0,%1,%2,%3};"
        : "+f"(d[0]), "+f"(d[1]), "+f"(d[2]), "+f"(d[3])
        : "r"(a[0]), "r"(a[1]), "r"(a[2]), "r"(a[3]), "r"(b[0]), "r"(b[1]));
}

// ================= prep: fp32 -> fp16 (x then w, one launch) =================
__global__ void prep_kernel(const float* __restrict__ x,
                            const float* __restrict__ w,
                            int n4x, int n4tot)
{
    int i = blockIdx.x * blockDim.x + threadIdx.x;
    if (i >= n4tot) return;
    const float* src;
    __half* dst;
    int idx;
    if (i < n4x) { src = x; dst = g_A; idx = i; }
    else         { src = w; dst = g_B; idx = i - n4x; }
    float4 v = reinterpret_cast<const float4*>(src)[idx];
    ushort4 o;
    o.x = ((__half_raw)__float2half_rn(v.x)).x;
    o.y = ((__half_raw)__float2half_rn(v.y)).x;
    o.z = ((__half_raw)__float2half_rn(v.z)).x;
    o.w = ((__half_raw)__float2half_rn(v.w)).x;
    reinterpret_cast<ushort4*>(dst)[idx] = o;
}

// ================= main GEMM kernel =================
__global__ void __launch_bounds__(512, 1)
qgemm_fp16(const float* __restrict__ bias, float* __restrict__ C)
{
    extern __shared__ char smem[];
    const uint32_t sbase = smem_u32(smem);
    const int tid  = threadIdx.x;
    const int wid  = tid >> 5;
    const int lane = tid & 31;
    const int bm = blockIdx.y * BM;
    const int bn = blockIdx.x * BN;
    const int wm = (wid >> 2) * 32;   // warp row offset (0,32,64,96)
    const int wn = (wid & 3) * 32;    // warp col offset (0,32,64,96)

    float acc[2][4][4];
    #pragma unroll
    for (int a = 0; a < 2; a++)
        #pragma unroll
        for (int b = 0; b < 4; b++)
            #pragma unroll
            for (int k = 0; k < 4; k++)
                acc[a][b][k] = 0.0f;

    // loader: 512 threads x 2 planes x 16B = 16KB/stage
    const int lrow = tid >> 2;        // 0..127
    const int lc   = tid & 3;
    const uint32_t dsw = SWZ((uint32_t)(lrow * 64 + lc * 16));
    const char* pA = (const char*)g_A + (size_t)(bm + lrow) * (KDIM * 2) + lc * 16;
    const char* pB = (const char*)g_B + (size_t)(bn + lrow) * (KDIM * 2) + lc * 16;

    auto issue = [&](int chunk) {
        const uint32_t sst = sbase + (chunk % STAGES) * STAGEB;
        const size_t ko = (size_t)chunk * (BK * 2);
        cp16(sst + OFF_A + dsw, pA + ko);
        cp16(sst + OFF_B + dsw, pB + ko);
        CP_COMMIT();
    };
    issue(0); issue(1); issue(2); issue(3);

    // ldmatrix fragment offsets (plane-relative, swizzled), ks = k16 half
    uint32_t aoff[2][2], boff[2][2];
    #pragma unroll
    for (int mb = 0; mb < 2; mb++)
        #pragma unroll
        for (int ks = 0; ks < 2; ks++)
            aoff[mb][ks] = SWZ((uint32_t)((wm + mb * 16 + (lane & 15)) * 64 +
                                          ks * 32 + (lane >> 4) * 16));
    #pragma unroll
    for (int p = 0; p < 2; p++)
        #pragma unroll
        for (int ks = 0; ks < 2; ks++)
            boff[p][ks] = SWZ((uint32_t)((wn + p * 16 + (lane & 7) + ((lane >> 4) << 3)) * 64 +
                                         ks * 32 + ((lane >> 3) & 1) * 16));

    auto do_ks = [&](int chunk, int ks) {
        const uint32_t sst = sbase + (chunk % STAGES) * STAGEB;
        uint32_t bh[4][2];
        #pragma unroll
        for (int p = 0; p < 2; p++) {
            uint32_t r[4];
            ldm_x4(r, sst + OFF_B + boff[p][ks]);
            bh[p*2][0] = r[0]; bh[p*2][1] = r[1];
            bh[p*2+1][0] = r[2]; bh[p*2+1][1] = r[3];
        }
        #pragma unroll
        for (int mb = 0; mb < 2; mb++) {
            uint32_t ah[4];
            ldm_x4(ah, sst + OFF_A + aoff[mb][ks]);
            #pragma unroll
            for (int nb = 0; nb < 4; nb++)
                mma16816(acc[mb][nb], ah, bh[nb]);
        }
    };

    for (int p = 0; p < NPAIR; p++) {
        const int c = 2 * p;
        if (p == NPAIR - 1) { CP_WAIT0(); } else { CP_WAIT2(); }
        __syncthreads();

        do_ks(c, 0);     do_ks(c, 1);
        do_ks(c + 1, 0); do_ks(c + 1, 1);

        if (c + 4 < NCHUNK) issue(c + 4);
        if (c + 5 < NCHUNK) issue(c + 5);
    }

    // -------- epilogue: + bias, store --------
    const int g  = lane >> 2;
    const int tg = lane & 3;
    #pragma unroll
    for (int mb = 0; mb < 2; mb++) {
        #pragma unroll
        for (int nb = 0; nb < 4; nb++) {
            const int col = bn + wn + nb * 8 + tg * 2;
            const float2 bv = *reinterpret_cast<const float2*>(bias + col);
            const int r0 = bm + wm + mb * 16 + g;
            float2 o0 = {acc[mb][nb][0] + bv.x, acc[mb][nb][1] + bv.y};
            float2 o1 = {acc[mb][nb][2] + bv.x, acc[mb][nb][3] + bv.y};
            *reinterpret_cast<float2*>(C + (size_t)r0 * NDIM + col) = o0;
            *reinterpret_cast<float2*>(C + (size_t)(r0 + 8) * NDIM + col) = o1;
        }
    }
}

// ================= host side =================
extern "C" void kernel_launch(void* const* d_in, const int* in_sizes, int n_in,
                              void* d_out, int out_size)
{
    const float* x    = (const float*)d_in[0];   // [M, K]
    const float* w    = (const float*)d_in[1];   // [N, K]
    const float* bias = (const float*)d_in[2];   // [N]
    float* out        = (float*)d_out;           // [M, N]

    const int n4x = MDIM * KDIM / 4;
    const int n4w = NDIM * KDIM / 4;
    const int n4tot = n4x + n4w;
    prep_kernel<<<(n4tot + 255) / 256, 256>>>(x, w, n4x, n4tot);

    static bool attr_set = false;
    if (!attr_set) {
        cudaFuncSetAttribute(qgemm_fp16, cudaFuncAttributeMaxDynamicSharedMemorySize, SMEM_TOTAL);
        attr_set = true;
    }
    dim3 grid(NDIM / BN, MDIM / BM);   // (32, 64) = 2048 CTAs
    qgemm_fp16<<<grid, 512, SMEM_TOTAL>>>(bias, out);
}

// round 11
// speedup vs baseline: 7.4406x; 1.2540x over previous
#include <cuda_runtime.h>
#include <cuda_fp16.h>
#include <cstdint>

// out[M,N] = x[M,K] @ W[N,K]^T + bias ; M=8192, N=4096, K=1024 (fp32)
// Round 11: single-pass fp16 HMMA, 256x128 CTA tile, 64x32 warp tiles.
// LDSM traffic drops 256->192 B/MMA so smem BW (128 B/cyc/SM) no longer
// binds; HMMA floor is 2 cyc/MMA/SM => ~113us ideal, ~170-185us expected.

#define MDIM 8192
#define NDIM 4096
#define KDIM 1024

#define BM 256
#define BN 128
#define BK 32                 // fp16: 64 B per row per plane
#define STAGES 6
#define NCHUNK (KDIM / BK)    // 32
#define NPAIR (NCHUNK / 2)    // 16

#define APLANEB (BM * 64)     // 16384 B
#define BPLANEB (BN * 64)     // 8192 B
#define OFF_A 0
#define OFF_B (APLANEB)
#define STAGEB (APLANEB + BPLANEB)    // 24576
#define SMEM_TOTAL (STAGES * STAGEB)  // 147456

// XOR swizzle on 16B chunks within 64B rows (conflict-free ldmatrix + cp.async)
#define SWZ(a) ((a) ^ (((a) >> 3) & 0x30))

// ---- static scratch for fp16 operands ----
__device__ __align__(256) __half g_A[MDIM * KDIM];
__device__ __align__(256) __half g_B[NDIM * KDIM];

// ================= PTX helpers (base PTX only) =================
__device__ __forceinline__ uint32_t smem_u32(const void* p) {
    uint32_t a;
    asm("{ .reg .u64 t; cvta.to.shared.u64 t, %1; cvt.u32.u64 %0, t; }" : "=r"(a) : "l"(p));
    return a;
}
__device__ __forceinline__ void cp16(uint32_t dst, const void* src) {
    asm volatile("cp.async.cg.shared.global [%0], [%1], 16;" :: "r"(dst), "l"(src));
}
#define CP_COMMIT() asm volatile("cp.async.commit_group;" ::: "memory")
#define CP_WAIT2()  asm volatile("cp.async.wait_group 2;"  ::: "memory")
#define CP_WAIT0()  asm volatile("cp.async.wait_group 0;"  ::: "memory")

__device__ __forceinline__ void ldm_x4(uint32_t* r, uint32_t addr) {
    asm volatile("ldmatrix.sync.aligned.m8n8.x4.shared.b16 {%0,%1,%2,%3}, [%4];"
        : "=r"(r[0]), "=r"(r[1]), "=r"(r[2]), "=r"(r[3]) : "r"(addr));
}
__device__ __forceinline__ void mma16816(float* d, const uint32_t* a, const uint32_t* b) {
    asm volatile("mma.sync.aligned.m16n8k16.row.col.f32.f16.f16.f32 "
        "{%0,%1,%2,%3}, {%4,%5,%6,%7}, {%8,%9}, {%0,%1,%2,%3};"
        : "+f"(d[0]), "+f"(d[1]), "+f"(d[2]), "+f"(d[3])
        : "r"(a[0]), "r"(a[1]), "r"(a[2]), "r"(a[3]), "r"(b[0]), "r"(b[1]));
}

// ================= prep: fp32 -> fp16 (x then w, one launch) =================
__global__ void prep_kernel(const float* __restrict__ x,
                            const float* __restrict__ w,
                            int n4x, int n4tot)
{
    int i = blockIdx.x * blockDim.x + threadIdx.x;
    if (i >= n4tot) return;
    const float* src;
    __half* dst;
    int idx;
    if (i < n4x) { src = x; dst = g_A; idx = i; }
    else         { src = w; dst = g_B; idx = i - n4x; }
    float4 v = reinterpret_cast<const float4*>(src)[idx];
    ushort4 o;
    o.x = ((__half_raw)__float2half_rn(v.x)).x;
    o.y = ((__half_raw)__float2half_rn(v.y)).x;
    o.z = ((__half_raw)__float2half_rn(v.z)).x;
    o.w = ((__half_raw)__float2half_rn(v.w)).x;
    reinterpret_cast<ushort4*>(dst)[idx] = o;
}

// ================= main GEMM kernel =================
__global__ void __launch_bounds__(512, 1)
qgemm_fp16(const float* __restrict__ bias, float* __restrict__ C)
{
    extern __shared__ char smem[];
    const uint32_t sbase = smem_u32(smem);
    const int tid  = threadIdx.x;
    const int wid  = tid >> 5;
    const int lane = tid & 31;
    const int bm = blockIdx.y * BM;
    const int bn = blockIdx.x * BN;
    const int wm = (wid >> 2) * 64;   // warp row offset (0,64,128,192)
    const int wn = (wid & 3) * 32;    // warp col offset (0,32,64,96)

    float acc[4][4][4];
    #pragma unroll
    for (int a = 0; a < 4; a++)
        #pragma unroll
        for (int b = 0; b < 4; b++)
            #pragma unroll
            for (int k = 0; k < 4; k++)
                acc[a][b][k] = 0.0f;

    // loader: A plane = 1024 16B-chunks (2/thread), B plane = 512 (1/thread)
    // A chunk id ca in {tid, tid+512}: row = ca>>2, col16 = ca&3
    // B chunk id cb = tid (tid<512): row = cb>>2, col16 = cb&3
    const int a0row = tid >> 2,           a0c = tid & 3;
    const int a1row = (tid + 512) >> 2,   a1c = tid & 3;   // +512 keeps col bits
    const uint32_t dswA0 = SWZ((uint32_t)(a0row * 64 + a0c * 16));
    const uint32_t dswA1 = SWZ((uint32_t)(a1row * 64 + a1c * 16));
    const uint32_t dswB  = dswA0;
    const char* pA0 = (const char*)g_A + (size_t)(bm + a0row) * (KDIM * 2) + a0c * 16;
    const char* pA1 = (const char*)g_A + (size_t)(bm + a1row) * (KDIM * 2) + a1c * 16;
    const char* pB  = (const char*)g_B + (size_t)(bn + a0row) * (KDIM * 2) + a0c * 16;

    auto issue = [&](int chunk) {
        const uint32_t sst = sbase + (chunk % STAGES) * STAGEB;
        const size_t ko = (size_t)chunk * (BK * 2);
        cp16(sst + OFF_A + dswA0, pA0 + ko);
        cp16(sst + OFF_A + dswA1, pA1 + ko);
        cp16(sst + OFF_B + dswB,  pB + ko);
        CP_COMMIT();
    };
    issue(0); issue(1); issue(2); issue(3);

    // ldmatrix fragment offsets (plane-relative, swizzled), ks = k16 half
    uint32_t aoff[4][2], boff[2][2];
    #pragma unroll
    for (int mb = 0; mb < 4; mb++)
        #pragma unroll
        for (int ks = 0; ks < 2; ks++)
            aoff[mb][ks] = SWZ((uint32_t)((wm + mb * 16 + (lane & 15)) * 64 +
                                          ks * 32 + (lane >> 4) * 16));
    #pragma unroll
    for (int p = 0; p < 2; p++)
        #pragma unroll
        for (int ks = 0; ks < 2; ks++)
            boff[p][ks] = SWZ((uint32_t)((wn + p * 16 + (lane & 7) + ((lane >> 4) << 3)) * 64 +
                                         ks * 32 + ((lane >> 3) & 1) * 16));

    auto do_ks = [&](int chunk, int ks) {
        const uint32_t sst = sbase + (chunk % STAGES) * STAGEB;
        uint32_t bh[4][2];
        #pragma unroll
        for (int p = 0; p < 2; p++) {
            uint32_t r[4];
            ldm_x4(r, sst + OFF_B + boff[p][ks]);
            bh[p*2][0] = r[0]; bh[p*2][1] = r[1];
            bh[p*2+1][0] = r[2]; bh[p*2+1][1] = r[3];
        }
        #pragma unroll
        for (int mb = 0; mb < 4; mb++) {
            uint32_t ah[4];
            ldm_x4(ah, sst + OFF_A + aoff[mb][ks]);
            #pragma unroll
            for (int nb = 0; nb < 4; nb++)
                mma16816(acc[mb][nb], ah, bh[nb]);
        }
    };

    for (int p = 0; p < NPAIR; p++) {
        const int c = 2 * p;
        if (p == NPAIR - 1) { CP_WAIT0(); } else { CP_WAIT2(); }
        __syncthreads();

        do_ks(c, 0);     do_ks(c, 1);
        do_ks(c + 1, 0); do_ks(c + 1, 1);

        if (c + 4 < NCHUNK) issue(c + 4);
        if (c + 5 < NCHUNK) issue(c + 5);
    }

    // -------- epilogue: + bias, store --------
    const int g  = lane >> 2;
    const int tg = lane & 3;
    #pragma unroll
    for (int mb = 0; mb < 4; mb++) {
        #pragma unroll
        for (int nb = 0; nb < 4; nb++) {
            const int col = bn + wn + nb * 8 + tg * 2;
            const float2 bv = *reinterpret_cast<const float2*>(bias + col);
            const int r0 = bm + wm + mb * 16 + g;
            float2 o0 = {acc[mb][nb][0] + bv.x, acc[mb][nb][1] + bv.y};
            float2 o1 = {acc[mb][nb][2] + bv.x, acc[mb][nb][3] + bv.y};
            *reinterpret_cast<float2*>(C + (size_t)r0 * NDIM + col) = o0;
            *reinterpret_cast<float2*>(C + (size_t)(r0 + 8) * NDIM + col) = o1;
        }
    }
}

// ================= host side =================
extern "C" void kernel_launch(void* const* d_in, const int* in_sizes, int n_in,
                              void* d_out, int out_size)
{
    const float* x    = (const float*)d_in[0];   // [M, K]
    const float* w    = (const float*)d_in[1];   // [N, K]
    const float* bias = (const float*)d_in[2];   // [N]
    float* out        = (float*)d_out;           // [M, N]

    const int n4x = MDIM * KDIM / 4;
    const int n4w = NDIM * KDIM / 4;
    const int n4tot = n4x + n4w;
    prep_kernel<<<(n4tot + 255) / 256, 256>>>(x, w, n4x, n4tot);

    static bool attr_set = false;
    if (!attr_set) {
        cudaFuncSetAttribute(qgemm_fp16, cudaFuncAttributeMaxDynamicSharedMemorySize, SMEM_TOTAL);
        attr_set = true;
    }
    dim3 grid(NDIM / BN, MDIM / BM);   // (32, 32) = 1024 CTAs
    qgemm_fp16<<<grid, 512, SMEM_TOTAL>>>(bias, out);
}